// round 1
// baseline (speedup 1.0000x reference)
#include <cuda_runtime.h>
#include <cuda_bf16.h>
#include <math.h>

#define T_    4096
#define HID_  4096
#define B_    4
#define S_    1024
#define H_    32
#define HKV_  8
#define D_    128
#define G_    4
#define NQKV_ 6144   // (H + 2*HKV) * D

// ---------------- scratch (static device allocations; no runtime alloc) ----
__device__ float g_qkv[(size_t)T_ * NQKV_];          // 100.7 MB
__device__ float g_q[(size_t)B_ * H_ * S_ * D_];     // 67 MB   [B,H,S,D]
__device__ float g_k[(size_t)B_ * HKV_ * S_ * D_];   // 16.8 MB [B,HKV,S,D]
__device__ float g_v[(size_t)B_ * HKV_ * S_ * D_];   // 16.8 MB
__device__ float g_attn[(size_t)T_ * HID_];          // 67 MB   [T, H*D]

// ---------------- GEMM: C[M,N] = A[M,K] * W[N,K]^T (both row-major) --------
__global__ __launch_bounds__(256) void sgemm_nt(
    const float* __restrict__ A, const float* __restrict__ Wt,
    float* __restrict__ C, int M, int N, int K)
{
    __shared__ float As[8][128];
    __shared__ float Bs[8][128];

    const int tid = threadIdx.x;
    const int bm  = blockIdx.y * 128;
    const int bn  = blockIdx.x * 128;
    const int tm  = (tid >> 4) << 3;   // 0..120
    const int tn  = (tid & 15) << 3;   // 0..120

    const int lr = tid >> 1;           // 0..127 row in tile
    const int lc = (tid & 1) << 2;     // 0 or 4

    const float* Ap = A  + (size_t)(bm + lr) * K + lc;
    const float* Wp = Wt + (size_t)(bn + lr) * K + lc;

    float acc[8][8];
    #pragma unroll
    for (int i = 0; i < 8; i++)
        #pragma unroll
        for (int j = 0; j < 8; j++) acc[i][j] = 0.f;

    for (int k0 = 0; k0 < K; k0 += 8) {
        float4 av = *(const float4*)(Ap + k0);
        float4 wv = *(const float4*)(Wp + k0);
        As[lc + 0][lr] = av.x; As[lc + 1][lr] = av.y;
        As[lc + 2][lr] = av.z; As[lc + 3][lr] = av.w;
        Bs[lc + 0][lr] = wv.x; Bs[lc + 1][lr] = wv.y;
        Bs[lc + 2][lr] = wv.z; Bs[lc + 3][lr] = wv.w;
        __syncthreads();

        #pragma unroll
        for (int kk = 0; kk < 8; kk++) {
            float ra[8], rb[8];
            #pragma unroll
            for (int i = 0; i < 4; i++) {
                float4 t4 = *(const float4*)(&As[kk][tm + i * 4]);
                // load in two float4s
                if (i < 2) { }
                (void)t4;
                break;
            }
            // explicit vector loads
            {
                float4 a0 = *(const float4*)(&As[kk][tm]);
                float4 a1 = *(const float4*)(&As[kk][tm + 4]);
                float4 b0 = *(const float4*)(&Bs[kk][tn]);
                float4 b1 = *(const float4*)(&Bs[kk][tn + 4]);
                ra[0]=a0.x; ra[1]=a0.y; ra[2]=a0.z; ra[3]=a0.w;
                ra[4]=a1.x; ra[5]=a1.y; ra[6]=a1.z; ra[7]=a1.w;
                rb[0]=b0.x; rb[1]=b0.y; rb[2]=b0.z; rb[3]=b0.w;
                rb[4]=b1.x; rb[5]=b1.y; rb[6]=b1.z; rb[7]=b1.w;
            }
            #pragma unroll
            for (int i = 0; i < 8; i++)
                #pragma unroll
                for (int j = 0; j < 8; j++)
                    acc[i][j] += ra[i] * rb[j];
        }
        __syncthreads();
    }

    #pragma unroll
    for (int i = 0; i < 8; i++) {
        float* Crow = C + (size_t)(bm + tm + i) * N + bn + tn;
        *(float4*)(Crow)     = make_float4(acc[i][0], acc[i][1], acc[i][2], acc[i][3]);
        *(float4*)(Crow + 4) = make_float4(acc[i][4], acc[i][5], acc[i][6], acc[i][7]);
    }
}

// ---------------- RoPE + scatter into [B,H,S,D] / [B,HKV,S,D] layouts ------
__global__ void rope_scatter(const float* __restrict__ qkv,
                             const int* __restrict__ positions,
                             float* __restrict__ Qr, float* __restrict__ Kr,
                             float* __restrict__ Vr)
{
    const int NQ = T_ * H_ * 64;     // 8388608
    const int NK = T_ * HKV_ * 64;   // 2097152
    const int NV = T_ * HKV_ * 128;  // 4194304
    int idx = blockIdx.x * 256 + threadIdx.x;

    // log2(10000)/64
    const double KF = 0.20762050593046014;

    if (idx < NQ) {
        int i = idx & 63;
        int h = (idx >> 6) & 31;
        int t = idx >> 11;
        int pos = positions[t];
        const float* row = qkv + (size_t)t * NQKV_ + h * 128;
        float x1 = row[i], x2 = row[64 + i];
        double f = (double)pos * exp2(-(double)i * KF);
        double sv, cv; sincos(f, &sv, &cv);
        float c = (float)cv, s = (float)sv;
        int b = t >> 10, si = t & 1023;
        float* out = Qr + (((size_t)(b * H_ + h)) * S_ + si) * 128;
        out[i]      = x1 * c - x2 * s;
        out[64 + i] = x2 * c + x1 * s;
    } else if (idx < NQ + NK) {
        int r = idx - NQ;
        int i = r & 63;
        int h = (r >> 6) & 7;
        int t = r >> 9;
        int pos = positions[t];
        const float* row = qkv + (size_t)t * NQKV_ + H_ * 128 + h * 128;
        float x1 = row[i], x2 = row[64 + i];
        double f = (double)pos * exp2(-(double)i * KF);
        double sv, cv; sincos(f, &sv, &cv);
        float c = (float)cv, s = (float)sv;
        int b = t >> 10, si = t & 1023;
        float* out = Kr + (((size_t)(b * HKV_ + h)) * S_ + si) * 128;
        out[i]      = x1 * c - x2 * s;
        out[64 + i] = x2 * c + x1 * s;
    } else if (idx < NQ + NK + NV) {
        int r = idx - NQ - NK;
        int i = r & 127;
        int h = (r >> 7) & 7;
        int t = r >> 10;
        int b = t >> 10, si = t & 1023;
        Vr[(((size_t)(b * HKV_ + h)) * S_ + si) * 128 + i] =
            qkv[(size_t)t * NQKV_ + (H_ + HKV_) * 128 + h * 128 + i];
    }
}

// ---------------- flash attention (causal, fp32, online softmax) -----------
// grid: (S/64, B*H); block: 256 threads
// smem: QsT[128][65] | Ks[64][128] | Vs[64][128] | Ss[64][65]
#define FL_QT  (128 * 65)
#define FL_KS  (64 * 128)
#define FL_VS  (64 * 128)
#define FL_SS  (64 * 65)
#define FL_SMEM_FLOATS (FL_QT + FL_KS + FL_VS + FL_SS)
#define FL_SMEM_BYTES  (FL_SMEM_FLOATS * 4)

__global__ __launch_bounds__(256) void flash_attn(
    const float* __restrict__ Q, const float* __restrict__ Kg,
    const float* __restrict__ Vg, float* __restrict__ Out)
{
    extern __shared__ float sm[];
    float* QsT = sm;                       // [128][65], QsT[d][r]
    float* Ks  = sm + FL_QT;               // [64][128]
    float* Vs  = Ks + FL_KS;               // [64][128]
    float* Ss  = Vs + FL_VS;               // [64][65]

    const int qb = blockIdx.x;             // 0..15
    const int bh = blockIdx.y;             // 0..127
    const int b  = bh >> 5;                // /H_
    const int h  = bh & 31;
    const int hkv = h >> 2;                // /G_

    const float* Qbase = Q  + ((size_t)bh * S_ + qb * 64) * D_;
    const float* Kbase = Kg + ((size_t)(b * HKV_ + hkv) * S_) * D_;
    const float* Vbase = Vg + ((size_t)(b * HKV_ + hkv) * S_) * D_;

    const int tid  = threadIdx.x;
    const int row  = tid & 63;
    const int grp  = tid >> 6;             // 0..3
    const int dcol = grp * 32;
    const int cbase = grp * 16;
    const int qpos = qb * 64 + row;
    const float SCALE = 0.08838834764831845f;  // 1/sqrt(128)

    // load Q tile transposed
    for (int i = tid; i < 64 * 32; i += 256) {
        int r = i >> 5, c = (i & 31) << 2;
        float4 v4 = *(const float4*)(Qbase + r * 128 + c);
        QsT[(c + 0) * 65 + r] = v4.x;
        QsT[(c + 1) * 65 + r] = v4.y;
        QsT[(c + 2) * 65 + r] = v4.z;
        QsT[(c + 3) * 65 + r] = v4.w;
    }

    float m = -1e30f, l = 0.f;
    float Oacc[32];
    #pragma unroll
    for (int i = 0; i < 32; i++) Oacc[i] = 0.f;

    for (int j = 0; j <= qb; j++) {
        __syncthreads();   // prior-iter smem reads done (also orders Q stores on iter 0)
        for (int i = tid; i < 64 * 32; i += 256) {
            int r = i >> 5, c = (i & 31) << 2;
            *(float4*)(&Ks[r * 128 + c]) = *(const float4*)(Kbase + (j * 64 + r) * 128 + c);
            *(float4*)(&Vs[r * 128 + c]) = *(const float4*)(Vbase + (j * 64 + r) * 128 + c);
        }
        __syncthreads();

        // scores: 16 per thread
        float s[16];
        #pragma unroll
        for (int c = 0; c < 16; c++) s[c] = 0.f;
        #pragma unroll 4
        for (int d = 0; d < 128; d++) {
            float qd = QsT[d * 65 + row];
            #pragma unroll
            for (int c = 0; c < 16; c++)
                s[c] += qd * Ks[(cbase + c) * 128 + d];
        }
        #pragma unroll
        for (int c = 0; c < 16; c++) {
            int kpos = j * 64 + cbase + c;
            float val = s[c] * SCALE;
            if (kpos > qpos) val = -1e30f;
            Ss[row * 65 + cbase + c] = val;
        }
        __syncthreads();

        // online softmax + PV
        float rmax = -1e30f;
        #pragma unroll 8
        for (int c = 0; c < 64; c++) rmax = fmaxf(rmax, Ss[row * 65 + c]);
        float mnew = fmaxf(m, rmax);
        float corr = __expf(m - mnew);
        l *= corr;
        #pragma unroll
        for (int i = 0; i < 32; i++) Oacc[i] *= corr;
        for (int c = 0; c < 64; c++) {
            float p = __expf(Ss[row * 65 + c] - mnew);
            l += p;
            const float* vrow = &Vs[c * 128 + dcol];
            #pragma unroll
            for (int i = 0; i < 32; i++) Oacc[i] += p * vrow[i];
        }
        m = mnew;
    }

    float inv_l = 1.f / l;
    float* orow = Out + ((size_t)(b * S_ + qpos)) * HID_ + h * 128 + dcol;
    #pragma unroll
    for (int i = 0; i < 32; i++) orow[i] = Oacc[i] * inv_l;
}

// ---------------- launch ---------------------------------------------------
extern "C" void kernel_launch(void* const* d_in, const int* in_sizes, int n_in,
                              void* d_out, int out_size)
{
    const int*   positions = (const int*)d_in[0];
    const float* hidden    = (const float*)d_in[1];
    const float* w_qkv     = (const float*)d_in[2];
    const float* w_dense   = (const float*)d_in[3];
    float*       out       = (float*)d_out;

    float *qkv, *q, *k, *v, *attn;
    cudaGetSymbolAddress((void**)&qkv,  g_qkv);
    cudaGetSymbolAddress((void**)&q,    g_q);
    cudaGetSymbolAddress((void**)&k,    g_k);
    cudaGetSymbolAddress((void**)&v,    g_v);
    cudaGetSymbolAddress((void**)&attn, g_attn);

    // 1) QKV projection
    dim3 g1(NQKV_ / 128, T_ / 128);
    sgemm_nt<<<g1, 256>>>(hidden, w_qkv, qkv, T_, NQKV_, HID_);

    // 2) RoPE + scatter
    const int n_rope = T_ * H_ * 64 + T_ * HKV_ * 64 + T_ * HKV_ * 128;
    rope_scatter<<<(n_rope + 255) / 256, 256>>>(qkv, positions, q, k, v);

    // 3) flash attention
    cudaFuncSetAttribute(flash_attn, cudaFuncAttributeMaxDynamicSharedMemorySize,
                         FL_SMEM_BYTES);
    flash_attn<<<dim3(S_ / 64, B_ * H_), 256, FL_SMEM_BYTES>>>(q, k, v, attn);

    // 4) dense projection
    dim3 g2(HID_ / 128, T_ / 128);
    sgemm_nt<<<g2, 256>>>(attn, w_dense, out, T_, HID_, HID_);
}

// round 3
// speedup vs baseline: 2.3718x; 2.3718x over previous
#include <cuda_runtime.h>
#include <cuda_bf16.h>
#include <cstdint>
#include <stdint.h>
#include <math.h>

#define T_    4096
#define HID_  4096
#define B_    4
#define S_    1024
#define H_    32
#define HKV_  8
#define D_    128
#define NQKV_ 6144   // (H + 2*HKV) * D

// ---------------- scratch ---------------------------------------------------
__device__ float g_qkv[(size_t)T_ * NQKV_];
__device__ float g_q[(size_t)B_ * H_ * S_ * D_];
__device__ float g_k[(size_t)B_ * HKV_ * S_ * D_];
__device__ float g_v[(size_t)B_ * HKV_ * S_ * D_];
__device__ float g_attn[(size_t)T_ * HID_];          // tf32-rounded by flash epilogue
__device__ float g_hid_r[(size_t)T_ * HID_];         // tf32-rounded activations
__device__ float g_wqkv_r[(size_t)NQKV_ * HID_];     // tf32-rounded weights
__device__ float g_wd_r[(size_t)HID_ * HID_];

// ---------------- helpers ---------------------------------------------------
__device__ __forceinline__ float to_tf32(float x) {
    unsigned int o;
    asm("cvt.rna.tf32.f32 %0, %1;" : "=r"(o) : "f"(x));
    return __uint_as_float(o);
}

__device__ __forceinline__ void cp16(unsigned int dst, const void* src) {
    asm volatile("cp.async.cg.shared.global [%0], [%1], 16;" :: "r"(dst), "l"(src));
}

__device__ __forceinline__ void mma_tf32(float* c, const unsigned int* a,
                                         const unsigned int* b) {
    asm volatile(
        "mma.sync.aligned.m16n8k8.row.col.f32.tf32.tf32.f32 "
        "{%0,%1,%2,%3}, {%4,%5,%6,%7}, {%8,%9}, {%0,%1,%2,%3};\n"
        : "+f"(c[0]), "+f"(c[1]), "+f"(c[2]), "+f"(c[3])
        : "r"(a[0]), "r"(a[1]), "r"(a[2]), "r"(a[3]), "r"(b[0]), "r"(b[1]));
}

// ---------------- pre-round fp32 -> tf32-canonical fp32 ---------------------
__global__ void round_tf32_kernel(const float* __restrict__ src,
                                  float* __restrict__ dst, int n4)
{
    int i = blockIdx.x * blockDim.x + threadIdx.x;
    if (i < n4) {
        float4 v = ((const float4*)src)[i];
        v.x = to_tf32(v.x); v.y = to_tf32(v.y);
        v.z = to_tf32(v.z); v.w = to_tf32(v.w);
        ((float4*)dst)[i] = v;
    }
}

// ---------------- tf32 tensor-core GEMM: C = A[M,K] * W[N,K]^T --------------
// inputs must already be tf32-canonical. 128x128x32 tiles, 8 warps (2Mx4N),
// warp tile 64x32, m16n8k8 mma, cp.async 2-stage pipeline.
#define BM 128
#define BN 128
#define BK 32
#define LDT 36   // smem row stride (floats): conflict-free frag loads
#define GEMM_SMEM_BYTES (2 * 2 * BM * LDT * 4)   // 73728

__global__ __launch_bounds__(256) void tf32_gemm_nt(
    const float* __restrict__ A, const float* __restrict__ W,
    float* __restrict__ C, int M, int N, int K)
{
    extern __shared__ float sm[];
    float* As = sm;                       // [2][128][36]
    float* Bs = sm + 2 * BM * LDT;        // [2][128][36]

    const int tid  = threadIdx.x;
    const int warp = tid >> 5, lane = tid & 31;
    const int g    = lane >> 2, t4 = lane & 3;
    const int wm   = (warp >> 2) * 64;    // warp M offset
    const int wn   = (warp & 3) * 32;     // warp N offset
    const int bm   = blockIdx.y * BM;
    const int bn   = blockIdx.x * BN;

    const unsigned int sA = (unsigned int)__cvta_generic_to_shared(As);
    const unsigned int sB = (unsigned int)__cvta_generic_to_shared(Bs);

    // per-thread load coords: 4 chunks of 16B per matrix per stage
    const int lr = tid >> 3;              // rows tid>>3, +32, +64, +96
    const int lcq = (tid & 7) * 4;        // col (floats)

    float acc[4][4][4];
    #pragma unroll
    for (int i = 0; i < 4; i++)
        #pragma unroll
        for (int j = 0; j < 4; j++)
            #pragma unroll
            for (int r = 0; r < 4; r++) acc[i][j][r] = 0.f;

    const int NT = K / BK;

    // prologue: load tile 0 into stage 0
    #pragma unroll
    for (int i = 0; i < 4; i++) {
        int r = lr + i * 32;
        cp16(sA + (unsigned int)((r * LDT + lcq) * 4),
             A + (size_t)(bm + r) * K + lcq);
        cp16(sB + (unsigned int)((r * LDT + lcq) * 4),
             W + (size_t)(bn + r) * K + lcq);
    }
    asm volatile("cp.async.commit_group;");

    for (int kt = 0; kt < NT; kt++) {
        const int buf = kt & 1;
        if (kt + 1 < NT) {
            const int nb = buf ^ 1;
            const int k0 = (kt + 1) * BK;
            #pragma unroll
            for (int i = 0; i < 4; i++) {
                int r = lr + i * 32;
                cp16(sA + (unsigned int)(((nb * BM + r) * LDT + lcq) * 4),
                     A + (size_t)(bm + r) * K + k0 + lcq);
                cp16(sB + (unsigned int)(((nb * BM + r) * LDT + lcq) * 4),
                     W + (size_t)(bn + r) * K + k0 + lcq);
            }
            asm volatile("cp.async.commit_group;");
            asm volatile("cp.async.wait_group 1;");
        } else {
            asm volatile("cp.async.wait_group 0;");
        }
        __syncthreads();

        const float* Ab = As + buf * BM * LDT;
        const float* Bb = Bs + buf * BM * LDT;

        #pragma unroll
        for (int kk = 0; kk < 4; kk++) {
            const int kc = kk * 8;
            unsigned int af[4][4], bf[4][2];
            #pragma unroll
            for (int mt = 0; mt < 4; mt++) {
                const int row = wm + mt * 16;
                af[mt][0] = __float_as_uint(Ab[(row + g)     * LDT + kc + t4]);
                af[mt][1] = __float_as_uint(Ab[(row + g + 8) * LDT + kc + t4]);
                af[mt][2] = __float_as_uint(Ab[(row + g)     * LDT + kc + t4 + 4]);
                af[mt][3] = __float_as_uint(Ab[(row + g + 8) * LDT + kc + t4 + 4]);
            }
            #pragma unroll
            for (int nt = 0; nt < 4; nt++) {
                const int col = wn + nt * 8 + g;
                bf[nt][0] = __float_as_uint(Bb[col * LDT + kc + t4]);
                bf[nt][1] = __float_as_uint(Bb[col * LDT + kc + t4 + 4]);
            }
            #pragma unroll
            for (int mt = 0; mt < 4; mt++)
                #pragma unroll
                for (int nt = 0; nt < 4; nt++)
                    mma_tf32(acc[mt][nt], af[mt], bf[nt]);
        }
        __syncthreads();
    }

    // epilogue
    #pragma unroll
    for (int mt = 0; mt < 4; mt++) {
        #pragma unroll
        for (int nt = 0; nt < 4; nt++) {
            const int row0 = bm + wm + mt * 16 + g;
            const int col  = bn + wn + nt * 8 + 2 * t4;
            float2 v01 = make_float2(acc[mt][nt][0], acc[mt][nt][1]);
            float2 v23 = make_float2(acc[mt][nt][2], acc[mt][nt][3]);
            *(float2*)(C + (size_t)row0 * N + col)       = v01;
            *(float2*)(C + (size_t)(row0 + 8) * N + col) = v23;
        }
    }
}

// ---------------- RoPE + scatter --------------------------------------------
__global__ void rope_scatter(const float* __restrict__ qkv,
                             const int* __restrict__ positions,
                             float* __restrict__ Qr, float* __restrict__ Kr,
                             float* __restrict__ Vr)
{
    const int NQ = T_ * H_ * 64;
    const int NK = T_ * HKV_ * 64;
    const int NV = T_ * HKV_ * 128;
    int idx = blockIdx.x * 256 + threadIdx.x;
    const double KF = 0.20762050593046014;  // log2(10000)/64

    if (idx < NQ) {
        int i = idx & 63;
        int h = (idx >> 6) & 31;
        int t = idx >> 11;
        int pos = positions[t];
        const float* row = qkv + (size_t)t * NQKV_ + h * 128;
        float x1 = row[i], x2 = row[64 + i];
        double f = (double)pos * exp2(-(double)i * KF);
        double sv, cv; sincos(f, &sv, &cv);
        float c = (float)cv, s = (float)sv;
        int b = t >> 10, si = t & 1023;
        float* out = Qr + (((size_t)(b * H_ + h)) * S_ + si) * 128;
        out[i]      = x1 * c - x2 * s;
        out[64 + i] = x2 * c + x1 * s;
    } else if (idx < NQ + NK) {
        int r = idx - NQ;
        int i = r & 63;
        int h = (r >> 6) & 7;
        int t = r >> 9;
        int pos = positions[t];
        const float* row = qkv + (size_t)t * NQKV_ + H_ * 128 + h * 128;
        float x1 = row[i], x2 = row[64 + i];
        double f = (double)pos * exp2(-(double)i * KF);
        double sv, cv; sincos(f, &sv, &cv);
        float c = (float)cv, s = (float)sv;
        int b = t >> 10, si = t & 1023;
        float* out = Kr + (((size_t)(b * HKV_ + h)) * S_ + si) * 128;
        out[i]      = x1 * c - x2 * s;
        out[64 + i] = x2 * c + x1 * s;
    } else if (idx < NQ + NK + NV) {
        int r = idx - NQ - NK;
        int i = r & 127;
        int h = (r >> 7) & 7;
        int t = r >> 10;
        int b = t >> 10, si = t & 1023;
        Vr[(((size_t)(b * HKV_ + h)) * S_ + si) * 128 + i] =
            qkv[(size_t)t * NQKV_ + (H_ + HKV_) * 128 + h * 128 + i];
    }
}

// ---------------- flash attention (causal, fp32, online softmax) ------------
#define FL_QT  (128 * 65)
#define FL_KS  (64 * 128)
#define FL_VS  (64 * 128)
#define FL_SS  (64 * 65)
#define FL_SMEM_BYTES  ((FL_QT + FL_KS + FL_VS + FL_SS) * 4)

__global__ __launch_bounds__(256) void flash_attn(
    const float* __restrict__ Q, const float* __restrict__ Kg,
    const float* __restrict__ Vg, float* __restrict__ Out)
{
    extern __shared__ float sm[];
    float* QsT = sm;
    float* Ks  = sm + FL_QT;
    float* Vs  = Ks + FL_KS;
    float* Ss  = Vs + FL_VS;

    const int qb = blockIdx.x;
    const int bh = blockIdx.y;
    const int b  = bh >> 5;
    const int h  = bh & 31;
    const int hkv = h >> 2;

    const float* Qbase = Q  + ((size_t)bh * S_ + qb * 64) * D_;
    const float* Kbase = Kg + ((size_t)(b * HKV_ + hkv) * S_) * D_;
    const float* Vbase = Vg + ((size_t)(b * HKV_ + hkv) * S_) * D_;

    const int tid  = threadIdx.x;
    const int row  = tid & 63;
    const int grp  = tid >> 6;
    const int dcol = grp * 32;
    const int cbase = grp * 16;
    const int qpos = qb * 64 + row;
    const float SCALE = 0.08838834764831845f;

    for (int i = tid; i < 64 * 32; i += 256) {
        int r = i >> 5, c = (i & 31) << 2;
        float4 v4 = *(const float4*)(Qbase + r * 128 + c);
        QsT[(c + 0) * 65 + r] = v4.x;
        QsT[(c + 1) * 65 + r] = v4.y;
        QsT[(c + 2) * 65 + r] = v4.z;
        QsT[(c + 3) * 65 + r] = v4.w;
    }

    float m = -1e30f, l = 0.f;
    float Oacc[32];
    #pragma unroll
    for (int i = 0; i < 32; i++) Oacc[i] = 0.f;

    for (int j = 0; j <= qb; j++) {
        __syncthreads();
        for (int i = tid; i < 64 * 32; i += 256) {
            int r = i >> 5, c = (i & 31) << 2;
            *(float4*)(&Ks[r * 128 + c]) = *(const float4*)(Kbase + (j * 64 + r) * 128 + c);
            *(float4*)(&Vs[r * 128 + c]) = *(const float4*)(Vbase + (j * 64 + r) * 128 + c);
        }
        __syncthreads();

        float s[16];
        #pragma unroll
        for (int c = 0; c < 16; c++) s[c] = 0.f;
        #pragma unroll 4
        for (int d = 0; d < 128; d++) {
            float qd = QsT[d * 65 + row];
            #pragma unroll
            for (int c = 0; c < 16; c++)
                s[c] += qd * Ks[(cbase + c) * 128 + d];
        }
        #pragma unroll
        for (int c = 0; c < 16; c++) {
            int kpos = j * 64 + cbase + c;
            float val = s[c] * SCALE;
            if (kpos > qpos) val = -1e30f;
            Ss[row * 65 + cbase + c] = val;
        }
        __syncthreads();

        float rmax = -1e30f;
        #pragma unroll 8
        for (int c = 0; c < 64; c++) rmax = fmaxf(rmax, Ss[row * 65 + c]);
        float mnew = fmaxf(m, rmax);
        float corr = __expf(m - mnew);
        l *= corr;
        #pragma unroll
        for (int i = 0; i < 32; i++) Oacc[i] *= corr;
        for (int c = 0; c < 64; c++) {
            float p = __expf(Ss[row * 65 + c] - mnew);
            l += p;
            const float* vrow = &Vs[c * 128 + dcol];
            #pragma unroll
            for (int i = 0; i < 32; i++) Oacc[i] += p * vrow[i];
        }
        m = mnew;
    }

    float inv_l = 1.f / l;
    float* orow = Out + ((size_t)(b * S_ + qpos)) * HID_ + h * 128 + dcol;
    #pragma unroll
    for (int i = 0; i < 32; i++) orow[i] = to_tf32(Oacc[i] * inv_l);  // tf32 for dense GEMM
}

// ---------------- launch -----------------------------------------------------
extern "C" void kernel_launch(void* const* d_in, const int* in_sizes, int n_in,
                              void* d_out, int out_size)
{
    const int*   positions = (const int*)d_in[0];
    const float* hidden    = (const float*)d_in[1];
    const float* w_qkv     = (const float*)d_in[2];
    const float* w_dense   = (const float*)d_in[3];
    float*       out       = (float*)d_out;

    float *qkv, *q, *k, *v, *attn, *hid_r, *wqkv_r, *wd_r;
    cudaGetSymbolAddress((void**)&qkv,    g_qkv);
    cudaGetSymbolAddress((void**)&q,      g_q);
    cudaGetSymbolAddress((void**)&k,      g_k);
    cudaGetSymbolAddress((void**)&v,      g_v);
    cudaGetSymbolAddress((void**)&attn,   g_attn);
    cudaGetSymbolAddress((void**)&hid_r,  g_hid_r);
    cudaGetSymbolAddress((void**)&wqkv_r, g_wqkv_r);
    cudaGetSymbolAddress((void**)&wd_r,   g_wd_r);

    // 0) pre-round GEMM operands to canonical tf32
    {
        int n4;
        n4 = (T_ * HID_) / 4;
        round_tf32_kernel<<<(n4 + 255) / 256, 256>>>(hidden, hid_r, n4);
        n4 = (NQKV_ * HID_) / 4;
        round_tf32_kernel<<<(n4 + 255) / 256, 256>>>(w_qkv, wqkv_r, n4);
        n4 = (HID_ * HID_) / 4;
        round_tf32_kernel<<<(n4 + 255) / 256, 256>>>(w_dense, wd_r, n4);
    }

    // 1) QKV projection (tensor cores)
    cudaFuncSetAttribute(tf32_gemm_nt, cudaFuncAttributeMaxDynamicSharedMemorySize,
                         GEMM_SMEM_BYTES);
    tf32_gemm_nt<<<dim3(NQKV_ / BN, T_ / BM), 256, GEMM_SMEM_BYTES>>>(
        hid_r, wqkv_r, qkv, T_, NQKV_, HID_);

    // 2) RoPE + scatter
    const int n_rope = T_ * H_ * 64 + T_ * HKV_ * 64 + T_ * HKV_ * 128;
    rope_scatter<<<(n_rope + 255) / 256, 256>>>(qkv, positions, q, k, v);

    // 3) flash attention (epilogue emits tf32-rounded attn)
    cudaFuncSetAttribute(flash_attn, cudaFuncAttributeMaxDynamicSharedMemorySize,
                         FL_SMEM_BYTES);
    flash_attn<<<dim3(S_ / 64, B_ * H_), 256, FL_SMEM_BYTES>>>(q, k, v, attn);

    // 4) dense projection (tensor cores)
    tf32_gemm_nt<<<dim3(HID_ / BN, T_ / BM), 256, GEMM_SMEM_BYTES>>>(
        attn, wd_r, out, T_, HID_, HID_);
}

// round 5
// speedup vs baseline: 3.0810x; 1.2990x over previous
#include <cuda_runtime.h>
#include <cuda_bf16.h>
#include <cstdint>
#include <stdint.h>
#include <math.h>

#define T_    4096
#define HID_  4096
#define B_    4
#define S_    1024
#define H_    32
#define HKV_  8
#define D_    128
#define NQKV_ 6144   // (H + 2*HKV) * D

// ---------------- scratch ---------------------------------------------------
__device__ float g_qkv[(size_t)T_ * NQKV_];
__device__ float g_q[(size_t)B_ * H_ * S_ * D_];
__device__ float g_k[(size_t)B_ * HKV_ * S_ * D_];
__device__ float g_v[(size_t)B_ * HKV_ * S_ * D_];
__device__ float g_attn[(size_t)T_ * HID_];          // tf32-rounded by flash epilogue
__device__ float g_hid_r[(size_t)T_ * HID_];         // tf32-rounded activations
__device__ float g_wqkv_r[(size_t)NQKV_ * HID_];     // tf32-rounded weights
__device__ float g_wd_r[(size_t)HID_ * HID_];

// ---------------- helpers ---------------------------------------------------
__device__ __forceinline__ float to_tf32(float x) {
    unsigned int o;
    asm("cvt.rna.tf32.f32 %0, %1;" : "=r"(o) : "f"(x));
    return __uint_as_float(o);
}

__device__ __forceinline__ void cp16(unsigned int dst, const void* src) {
    asm volatile("cp.async.cg.shared.global [%0], [%1], 16;" :: "r"(dst), "l"(src));
}

__device__ __forceinline__ void mma_tf32(float* c, const unsigned int* a,
                                         const unsigned int* b) {
    asm volatile(
        "mma.sync.aligned.m16n8k8.row.col.f32.tf32.tf32.f32 "
        "{%0,%1,%2,%3}, {%4,%5,%6,%7}, {%8,%9}, {%0,%1,%2,%3};\n"
        : "+f"(c[0]), "+f"(c[1]), "+f"(c[2]), "+f"(c[3])
        : "r"(a[0]), "r"(a[1]), "r"(a[2]), "r"(a[3]), "r"(b[0]), "r"(b[1]));
}

// ---------------- pre-round fp32 -> tf32-canonical fp32 ---------------------
__global__ void round_tf32_kernel(const float* __restrict__ src,
                                  float* __restrict__ dst, int n4)
{
    int i = blockIdx.x * blockDim.x + threadIdx.x;
    if (i < n4) {
        float4 v = ((const float4*)src)[i];
        v.x = to_tf32(v.x); v.y = to_tf32(v.y);
        v.z = to_tf32(v.z); v.w = to_tf32(v.w);
        ((float4*)dst)[i] = v;
    }
}

// ---------------- tf32 tensor-core GEMM: C = A[M,K] * W[N,K]^T --------------
#define BM 128
#define BN 128
#define BK 32
#define LDT 36
#define GEMM_SMEM_BYTES (2 * 2 * BM * LDT * 4)   // 73728

__global__ __launch_bounds__(256) void tf32_gemm_nt(
    const float* __restrict__ A, const float* __restrict__ W,
    float* __restrict__ C, int M, int N, int K)
{
    extern __shared__ float sm[];
    float* As = sm;
    float* Bs = sm + 2 * BM * LDT;

    const int tid  = threadIdx.x;
    const int warp = tid >> 5, lane = tid & 31;
    const int g    = lane >> 2, t4 = lane & 3;
    const int wm   = (warp >> 2) * 64;
    const int wn   = (warp & 3) * 32;
    const int bm   = blockIdx.y * BM;
    const int bn   = blockIdx.x * BN;

    const unsigned int sA = (unsigned int)__cvta_generic_to_shared(As);
    const unsigned int sB = (unsigned int)__cvta_generic_to_shared(Bs);

    const int lr = tid >> 3;
    const int lcq = (tid & 7) * 4;

    float acc[4][4][4];
    #pragma unroll
    for (int i = 0; i < 4; i++)
        #pragma unroll
        for (int j = 0; j < 4; j++)
            #pragma unroll
            for (int r = 0; r < 4; r++) acc[i][j][r] = 0.f;

    const int NT = K / BK;

    #pragma unroll
    for (int i = 0; i < 4; i++) {
        int r = lr + i * 32;
        cp16(sA + (unsigned int)((r * LDT + lcq) * 4), A + (size_t)(bm + r) * K + lcq);
        cp16(sB + (unsigned int)((r * LDT + lcq) * 4), W + (size_t)(bn + r) * K + lcq);
    }
    asm volatile("cp.async.commit_group;");

    for (int kt = 0; kt < NT; kt++) {
        const int buf = kt & 1;
        if (kt + 1 < NT) {
            const int nb = buf ^ 1;
            const int k0 = (kt + 1) * BK;
            #pragma unroll
            for (int i = 0; i < 4; i++) {
                int r = lr + i * 32;
                cp16(sA + (unsigned int)(((nb * BM + r) * LDT + lcq) * 4),
                     A + (size_t)(bm + r) * K + k0 + lcq);
                cp16(sB + (unsigned int)(((nb * BM + r) * LDT + lcq) * 4),
                     W + (size_t)(bn + r) * K + k0 + lcq);
            }
            asm volatile("cp.async.commit_group;");
            asm volatile("cp.async.wait_group 1;");
        } else {
            asm volatile("cp.async.wait_group 0;");
        }
        __syncthreads();

        const float* Ab = As + buf * BM * LDT;
        const float* Bb = Bs + buf * BM * LDT;

        #pragma unroll
        for (int kk = 0; kk < 4; kk++) {
            const int kc = kk * 8;
            unsigned int af[4][4], bf[4][2];
            #pragma unroll
            for (int mt = 0; mt < 4; mt++) {
                const int row = wm + mt * 16;
                af[mt][0] = __float_as_uint(Ab[(row + g)     * LDT + kc + t4]);
                af[mt][1] = __float_as_uint(Ab[(row + g + 8) * LDT + kc + t4]);
                af[mt][2] = __float_as_uint(Ab[(row + g)     * LDT + kc + t4 + 4]);
                af[mt][3] = __float_as_uint(Ab[(row + g + 8) * LDT + kc + t4 + 4]);
            }
            #pragma unroll
            for (int nt = 0; nt < 4; nt++) {
                const int col = wn + nt * 8 + g;
                bf[nt][0] = __float_as_uint(Bb[col * LDT + kc + t4]);
                bf[nt][1] = __float_as_uint(Bb[col * LDT + kc + t4 + 4]);
            }
            #pragma unroll
            for (int mt = 0; mt < 4; mt++)
                #pragma unroll
                for (int nt = 0; nt < 4; nt++)
                    mma_tf32(acc[mt][nt], af[mt], bf[nt]);
        }
        __syncthreads();
    }

    #pragma unroll
    for (int mt = 0; mt < 4; mt++) {
        #pragma unroll
        for (int nt = 0; nt < 4; nt++) {
            const int row0 = bm + wm + mt * 16 + g;
            const int col  = bn + wn + nt * 8 + 2 * t4;
            *(float2*)(C + (size_t)row0 * N + col)       = make_float2(acc[mt][nt][0], acc[mt][nt][1]);
            *(float2*)(C + (size_t)(row0 + 8) * N + col) = make_float2(acc[mt][nt][2], acc[mt][nt][3]);
        }
    }
}

// ---------------- RoPE + scatter (emits tf32-canonical q/k/v) ---------------
__global__ void rope_scatter(const float* __restrict__ qkv,
                             const int* __restrict__ positions,
                             float* __restrict__ Qr, float* __restrict__ Kr,
                             float* __restrict__ Vr)
{
    const int NQ = T_ * H_ * 64;
    const int NK = T_ * HKV_ * 64;
    const int NV = T_ * HKV_ * 128;
    int idx = blockIdx.x * 256 + threadIdx.x;
    const double KF = 0.20762050593046014;  // log2(10000)/64

    if (idx < NQ) {
        int i = idx & 63;
        int h = (idx >> 6) & 31;
        int t = idx >> 11;
        int pos = positions[t];
        const float* row = qkv + (size_t)t * NQKV_ + h * 128;
        float x1 = row[i], x2 = row[64 + i];
        double f = (double)pos * exp2(-(double)i * KF);
        double sv, cv; sincos(f, &sv, &cv);
        float c = (float)cv, s = (float)sv;
        int b = t >> 10, si = t & 1023;
        float* out = Qr + (((size_t)(b * H_ + h)) * S_ + si) * 128;
        out[i]      = to_tf32(x1 * c - x2 * s);
        out[64 + i] = to_tf32(x2 * c + x1 * s);
    } else if (idx < NQ + NK) {
        int r = idx - NQ;
        int i = r & 63;
        int h = (r >> 6) & 7;
        int t = r >> 9;
        int pos = positions[t];
        const float* row = qkv + (size_t)t * NQKV_ + H_ * 128 + h * 128;
        float x1 = row[i], x2 = row[64 + i];
        double f = (double)pos * exp2(-(double)i * KF);
        double sv, cv; sincos(f, &sv, &cv);
        float c = (float)cv, s = (float)sv;
        int b = t >> 10, si = t & 1023;
        float* out = Kr + (((size_t)(b * HKV_ + h)) * S_ + si) * 128;
        out[i]      = to_tf32(x1 * c - x2 * s);
        out[64 + i] = to_tf32(x2 * c + x1 * s);
    } else if (idx < NQ + NK + NV) {
        int r = idx - NQ - NK;
        int i = r & 127;
        int h = (r >> 7) & 7;
        int t = r >> 10;
        int b = t >> 10, si = t & 1023;
        Vr[(((size_t)(b * HKV_ + h)) * S_ + si) * 128 + i] =
            to_tf32(qkv[(size_t)t * NQKV_ + (H_ + HKV_) * 128 + h * 128 + i]);
    }
}

// ---------------- flash attention via tf32 mma ------------------------------
// grid (S/128, B*H), 256 threads (8 warps x m16 rows). K tiles of 64.
#define FA_LDQ 132
#define FA_LDK 132
#define FA_LDV 136
#define FA_LDP 68
#define FA_Q_FLOATS (128 * FA_LDQ)
#define FA_K_FLOATS (64 * FA_LDK)
#define FA_V_FLOATS (64 * FA_LDV)
#define FA_P_FLOATS (128 * FA_LDP)
#define FA_SMEM_BYTES ((FA_Q_FLOATS + FA_K_FLOATS + FA_V_FLOATS + FA_P_FLOATS) * 4)

__global__ __launch_bounds__(256) void flash_attn_mma(
    const float* __restrict__ Q, const float* __restrict__ Kg,
    const float* __restrict__ Vg, float* __restrict__ Out)
{
    extern __shared__ float sm[];
    float* Qs = sm;
    float* Ks = Qs + FA_Q_FLOATS;
    float* Vs = Ks + FA_K_FLOATS;
    float* Ps = Vs + FA_V_FLOATS;

    const int qb = blockIdx.x;              // 0..7
    const int bh = blockIdx.y;              // 0..127
    const int b  = bh >> 5;
    const int h  = bh & 31;
    const int hkv = h >> 2;

    const float* Qbase = Q  + ((size_t)bh * S_ + qb * 128) * D_;
    const float* Kbase = Kg + ((size_t)(b * HKV_ + hkv) * S_) * D_;
    const float* Vbase = Vg + ((size_t)(b * HKV_ + hkv) * S_) * D_;

    const int tid  = threadIdx.x;
    const int w    = tid >> 5, lane = tid & 31;
    const int g    = lane >> 2, t4 = lane & 3;
    const int wrow = w * 16;
    // exp(x*scale) == exp2(x * C), C = (1/sqrt(128)) * log2(e)
    const float C = 0.12751743199276533f;

    // load Q tile (128x128) into padded smem
    for (int i = tid; i < 128 * 32; i += 256) {
        int r = i >> 5, c = (i & 31) << 2;
        *(float4*)&Qs[r * FA_LDQ + c] = *(const float4*)(Qbase + r * 128 + c);
    }

    float O[16][4];
    #pragma unroll
    for (int n = 0; n < 16; n++)
        #pragma unroll
        for (int r = 0; r < 4; r++) O[n][r] = 0.f;
    float m0 = -1e30f, m1 = -1e30f, l0 = 0.f, l1 = 0.f;

    const int jmax = 2 * qb + 1;
    for (int j = 0; j <= jmax; j++) {
        __syncthreads();   // prior PV reads of Ks/Vs done
        for (int i = tid; i < 64 * 32; i += 256) {
            int r = i >> 5, c = (i & 31) << 2;
            *(float4*)&Ks[r * FA_LDK + c] = *(const float4*)(Kbase + (j * 64 + r) * 128 + c);
            *(float4*)&Vs[r * FA_LDV + c] = *(const float4*)(Vbase + (j * 64 + r) * 128 + c);
        }
        __syncthreads();

        // warp fully above the causal frontier for this k-tile? skip compute
        if (j * 64 > qb * 128 + wrow + 15) continue;

        // ---- S = Q Kt (16 rows x 64 cols per warp) ----
        float sfr[8][4];
        #pragma unroll
        for (int n = 0; n < 8; n++)
            #pragma unroll
            for (int r = 0; r < 4; r++) sfr[n][r] = 0.f;

        #pragma unroll
        for (int kc = 0; kc < 16; kc++) {
            const int k8 = kc * 8;
            unsigned int a[4];
            a[0] = __float_as_uint(Qs[(wrow + g)     * FA_LDQ + k8 + t4]);
            a[1] = __float_as_uint(Qs[(wrow + g + 8) * FA_LDQ + k8 + t4]);
            a[2] = __float_as_uint(Qs[(wrow + g)     * FA_LDQ + k8 + t4 + 4]);
            a[3] = __float_as_uint(Qs[(wrow + g + 8) * FA_LDQ + k8 + t4 + 4]);
            #pragma unroll
            for (int nt = 0; nt < 8; nt++) {
                unsigned int bfr[2];
                bfr[0] = __float_as_uint(Ks[(nt * 8 + g) * FA_LDK + k8 + t4]);
                bfr[1] = __float_as_uint(Ks[(nt * 8 + g) * FA_LDK + k8 + t4 + 4]);
                mma_tf32(sfr[nt], a, bfr);
            }
        }

        // ---- causal mask (raw-score domain) ----
        const int qpos0 = qb * 128 + wrow + g;
        const int qpos1 = qpos0 + 8;
        if (j * 64 + 63 > qb * 128 + wrow) {
            #pragma unroll
            for (int nt = 0; nt < 8; nt++) {
                const int kc0 = j * 64 + nt * 8 + 2 * t4;
                if (kc0     > qpos0) sfr[nt][0] = -1e30f;
                if (kc0 + 1 > qpos0) sfr[nt][1] = -1e30f;
                if (kc0     > qpos1) sfr[nt][2] = -1e30f;
                if (kc0 + 1 > qpos1) sfr[nt][3] = -1e30f;
            }
        }

        // ---- online softmax ----
        float rm0 = -1e30f, rm1 = -1e30f;
        #pragma unroll
        for (int nt = 0; nt < 8; nt++) {
            rm0 = fmaxf(rm0, fmaxf(sfr[nt][0], sfr[nt][1]));
            rm1 = fmaxf(rm1, fmaxf(sfr[nt][2], sfr[nt][3]));
        }
        rm0 = fmaxf(rm0, __shfl_xor_sync(0xffffffffu, rm0, 1));
        rm0 = fmaxf(rm0, __shfl_xor_sync(0xffffffffu, rm0, 2));
        rm1 = fmaxf(rm1, __shfl_xor_sync(0xffffffffu, rm1, 1));
        rm1 = fmaxf(rm1, __shfl_xor_sync(0xffffffffu, rm1, 2));

        const float mn0 = fmaxf(m0, rm0);
        const float mn1 = fmaxf(m1, rm1);
        const float corr0 = exp2f((m0 - mn0) * C);
        const float corr1 = exp2f((m1 - mn1) * C);
        #pragma unroll
        for (int nt = 0; nt < 16; nt++) {
            O[nt][0] *= corr0; O[nt][1] *= corr0;
            O[nt][2] *= corr1; O[nt][3] *= corr1;
        }

        float ls0 = 0.f, ls1 = 0.f;
        #pragma unroll
        for (int nt = 0; nt < 8; nt++) {
            float p00 = to_tf32(exp2f((sfr[nt][0] - mn0) * C));
            float p01 = to_tf32(exp2f((sfr[nt][1] - mn0) * C));
            float p10 = to_tf32(exp2f((sfr[nt][2] - mn1) * C));
            float p11 = to_tf32(exp2f((sfr[nt][3] - mn1) * C));
            ls0 += p00 + p01;
            ls1 += p10 + p11;
            const int col = nt * 8 + 2 * t4;
            *(float2*)&Ps[(wrow + g)     * FA_LDP + col] = make_float2(p00, p01);
            *(float2*)&Ps[(wrow + g + 8) * FA_LDP + col] = make_float2(p10, p11);
        }
        ls0 += __shfl_xor_sync(0xffffffffu, ls0, 1);
        ls0 += __shfl_xor_sync(0xffffffffu, ls0, 2);
        ls1 += __shfl_xor_sync(0xffffffffu, ls1, 1);
        ls1 += __shfl_xor_sync(0xffffffffu, ls1, 2);
        l0 = l0 * corr0 + ls0;
        l1 = l1 * corr1 + ls1;
        m0 = mn0; m1 = mn1;

        __syncwarp();   // P rows are warp-private: warp-level visibility suffices

        // ---- O += P V ----
        #pragma unroll
        for (int kc = 0; kc < 8; kc++) {
            const int k8 = kc * 8;
            unsigned int a[4];
            a[0] = __float_as_uint(Ps[(wrow + g)     * FA_LDP + k8 + t4]);
            a[1] = __float_as_uint(Ps[(wrow + g + 8) * FA_LDP + k8 + t4]);
            a[2] = __float_as_uint(Ps[(wrow + g)     * FA_LDP + k8 + t4 + 4]);
            a[3] = __float_as_uint(Ps[(wrow + g + 8) * FA_LDP + k8 + t4 + 4]);
            #pragma unroll
            for (int nt = 0; nt < 16; nt++) {
                unsigned int bfr[2];
                bfr[0] = __float_as_uint(Vs[(k8 + t4)     * FA_LDV + nt * 8 + g]);
                bfr[1] = __float_as_uint(Vs[(k8 + t4 + 4) * FA_LDV + nt * 8 + g]);
                mma_tf32(O[nt], a, bfr);
            }
        }
    }

    // ---- epilogue: normalize, round to tf32, store to attn [T, H*D] ----
    const float il0 = 1.f / l0;
    const float il1 = 1.f / l1;
    const int trow = b * S_ + qb * 128 + wrow + g;
    float* o0 = Out + (size_t)trow * HID_ + h * 128;
    float* o1 = o0 + (size_t)8 * HID_;
    #pragma unroll
    for (int nt = 0; nt < 16; nt++) {
        const int col = nt * 8 + 2 * t4;
        *(float2*)(o0 + col) = make_float2(to_tf32(O[nt][0] * il0), to_tf32(O[nt][1] * il0));
        *(float2*)(o1 + col) = make_float2(to_tf32(O[nt][2] * il1), to_tf32(O[nt][3] * il1));
    }
}

// ---------------- launch -----------------------------------------------------
extern "C" void kernel_launch(void* const* d_in, const int* in_sizes, int n_in,
                              void* d_out, int out_size)
{
    const int*   positions = (const int*)d_in[0];
    const float* hidden    = (const float*)d_in[1];
    const float* w_qkv     = (const float*)d_in[2];
    const float* w_dense   = (const float*)d_in[3];
    float*       out       = (float*)d_out;

    float *qkv, *q, *k, *v, *attn, *hid_r, *wqkv_r, *wd_r;
    cudaGetSymbolAddress((void**)&qkv,    g_qkv);
    cudaGetSymbolAddress((void**)&q,      g_q);
    cudaGetSymbolAddress((void**)&k,      g_k);
    cudaGetSymbolAddress((void**)&v,      g_v);
    cudaGetSymbolAddress((void**)&attn,   g_attn);
    cudaGetSymbolAddress((void**)&hid_r,  g_hid_r);
    cudaGetSymbolAddress((void**)&wqkv_r, g_wqkv_r);
    cudaGetSymbolAddress((void**)&wd_r,   g_wd_r);

    // 0) pre-round GEMM operands to canonical tf32
    {
        int n4;
        n4 = (T_ * HID_) / 4;
        round_tf32_kernel<<<(n4 + 255) / 256, 256>>>(hidden, hid_r, n4);
        n4 = (NQKV_ * HID_) / 4;
        round_tf32_kernel<<<(n4 + 255) / 256, 256>>>(w_qkv, wqkv_r, n4);
        n4 = (HID_ * HID_) / 4;
        round_tf32_kernel<<<(n4 + 255) / 256, 256>>>(w_dense, wd_r, n4);
    }

    // 1) QKV projection
    cudaFuncSetAttribute(tf32_gemm_nt, cudaFuncAttributeMaxDynamicSharedMemorySize,
                         GEMM_SMEM_BYTES);
    tf32_gemm_nt<<<dim3(NQKV_ / BN, T_ / BM), 256, GEMM_SMEM_BYTES>>>(
        hid_r, wqkv_r, qkv, T_, NQKV_, HID_);

    // 2) RoPE + scatter (tf32-canonical outputs)
    const int n_rope = T_ * H_ * 64 + T_ * HKV_ * 64 + T_ * HKV_ * 128;
    rope_scatter<<<(n_rope + 255) / 256, 256>>>(qkv, positions, q, k, v);

    // 3) flash attention on tensor cores
    cudaFuncSetAttribute(flash_attn_mma, cudaFuncAttributeMaxDynamicSharedMemorySize,
                         FA_SMEM_BYTES);
    flash_attn_mma<<<dim3(S_ / 128, B_ * H_), 256, FA_SMEM_BYTES>>>(q, k, v, attn);

    // 4) dense projection
    tf32_gemm_nt<<<dim3(HID_ / BN, T_ / BM), 256, GEMM_SMEM_BYTES>>>(
        attn, wd_r, out, T_, HID_, HID_);
}

// round 6
// speedup vs baseline: 3.2856x; 1.0664x over previous
#include <cuda_runtime.h>
#include <cuda_bf16.h>
#include <cstdint>
#include <stdint.h>
#include <math.h>

#define T_    4096
#define HID_  4096
#define B_    4
#define S_    1024
#define H_    32
#define HKV_  8
#define D_    128
#define NQKV_ 6144   // (H + 2*HKV) * D

// ---------------- scratch ---------------------------------------------------
__device__ float g_qkv[(size_t)T_ * NQKV_];
__device__ float g_q[(size_t)B_ * H_ * S_ * D_];
__device__ float g_k[(size_t)B_ * HKV_ * S_ * D_];
__device__ float g_v[(size_t)B_ * HKV_ * S_ * D_];
__device__ float g_attn[(size_t)T_ * HID_];
__device__ float g_hid_r[(size_t)T_ * HID_];
__device__ float g_wqkv_r[(size_t)NQKV_ * HID_];
__device__ float g_wd_r[(size_t)HID_ * HID_];

// ---------------- helpers ---------------------------------------------------
__device__ __forceinline__ float to_tf32(float x) {
    unsigned int o;
    asm("cvt.rna.tf32.f32 %0, %1;" : "=r"(o) : "f"(x));
    return __uint_as_float(o);
}

__device__ __forceinline__ void cp16(unsigned int dst, const void* src) {
    asm volatile("cp.async.cg.shared.global [%0], [%1], 16;" :: "r"(dst), "l"(src));
}

__device__ __forceinline__ void mma_tf32(float* c, const unsigned int* a,
                                         const unsigned int* b) {
    asm volatile(
        "mma.sync.aligned.m16n8k8.row.col.f32.tf32.tf32.f32 "
        "{%0,%1,%2,%3}, {%4,%5,%6,%7}, {%8,%9}, {%0,%1,%2,%3};\n"
        : "+f"(c[0]), "+f"(c[1]), "+f"(c[2]), "+f"(c[3])
        : "r"(a[0]), "r"(a[1]), "r"(a[2]), "r"(a[3]), "r"(b[0]), "r"(b[1]));
}

// ldmatrix x4: four 8x8 b16 tiles (= four 8x4 tf32 tiles). addr is a shared-
// space byte address; 16B-aligned per-lane row pointers.
__device__ __forceinline__ void ldsm4(unsigned int* r, unsigned int addr) {
    asm volatile("ldmatrix.sync.aligned.m8n8.x4.shared.b16 {%0,%1,%2,%3}, [%4];"
        : "=r"(r[0]), "=r"(r[1]), "=r"(r[2]), "=r"(r[3]) : "r"(addr));
}

// ---------------- pre-round fp32 -> tf32-canonical fp32 ---------------------
__global__ void round_tf32_kernel(const float* __restrict__ src,
                                  float* __restrict__ dst, int n4)
{
    int i = blockIdx.x * blockDim.x + threadIdx.x;
    if (i < n4) {
        float4 v = ((const float4*)src)[i];
        v.x = to_tf32(v.x); v.y = to_tf32(v.y);
        v.z = to_tf32(v.z); v.w = to_tf32(v.w);
        ((float4*)dst)[i] = v;
    }
}

// ---------------- tf32 tensor-core GEMM: C = A[M,K] * W[N,K]^T --------------
#define BM 128
#define BN 128
#define BK 32
#define LDT 36
#define GEMM_STAGE_BYTES (BM * LDT * 4)              // one matrix, one stage
#define GEMM_SMEM_BYTES (2 * 2 * BM * LDT * 4)       // 73728

__global__ __launch_bounds__(256) void tf32_gemm_nt(
    const float* __restrict__ A, const float* __restrict__ W,
    float* __restrict__ C, int M, int N, int K)
{
    extern __shared__ float sm[];
    float* As = sm;                         // [2][128][36]
    float* Bs = sm + 2 * BM * LDT;          // [2][128][36]

    const int tid  = threadIdx.x;
    const int warp = tid >> 5, lane = tid & 31;
    const int wm   = (warp >> 2) * 64;
    const int wn   = (warp & 3) * 32;
    const int bm   = blockIdx.y * BM;
    const int bn   = blockIdx.x * BN;

    const unsigned int sA = (unsigned int)__cvta_generic_to_shared(As);
    const unsigned int sB = (unsigned int)__cvta_generic_to_shared(Bs);

    // ldmatrix lane address components
    const int l7  = lane & 7;
    const int lg1 = (lane >> 3) & 1;
    const int lg2 = lane >> 4;
    // A frag: row += 8*lg1, col += 4*lg2 ; B frag: row += 8*lg2, col += 4*lg1
    const unsigned int aLane = (unsigned int)(((wm + l7 + 8 * lg1) * LDT + 4 * lg2) * 4);
    const unsigned int bLane = (unsigned int)(((wn + l7 + 8 * lg2) * LDT + 4 * lg1) * 4);

    const int lr = tid >> 3;
    const int lcq = (tid & 7) * 4;

    float acc[4][4][4];
    #pragma unroll
    for (int i = 0; i < 4; i++)
        #pragma unroll
        for (int j = 0; j < 4; j++)
            #pragma unroll
            for (int r = 0; r < 4; r++) acc[i][j][r] = 0.f;

    const int NT = K / BK;

    #pragma unroll
    for (int i = 0; i < 4; i++) {
        int r = lr + i * 32;
        cp16(sA + (unsigned int)((r * LDT + lcq) * 4), A + (size_t)(bm + r) * K + lcq);
        cp16(sB + (unsigned int)((r * LDT + lcq) * 4), W + (size_t)(bn + r) * K + lcq);
    }
    asm volatile("cp.async.commit_group;");

    for (int kt = 0; kt < NT; kt++) {
        const int buf = kt & 1;
        if (kt + 1 < NT) {
            const int nb = buf ^ 1;
            const int k0 = (kt + 1) * BK;
            #pragma unroll
            for (int i = 0; i < 4; i++) {
                int r = lr + i * 32;
                cp16(sA + (unsigned int)(((nb * BM + r) * LDT + lcq) * 4),
                     A + (size_t)(bm + r) * K + k0 + lcq);
                cp16(sB + (unsigned int)(((nb * BM + r) * LDT + lcq) * 4),
                     W + (size_t)(bn + r) * K + k0 + lcq);
            }
            asm volatile("cp.async.commit_group;");
            asm volatile("cp.async.wait_group 1;");
        } else {
            asm volatile("cp.async.wait_group 0;");
        }
        __syncthreads();

        const unsigned int aBase = sA + (unsigned int)(buf * GEMM_STAGE_BYTES) + aLane;
        const unsigned int bBase = sB + (unsigned int)(buf * GEMM_STAGE_BYTES) + bLane;

        #pragma unroll
        for (int kk = 0; kk < 4; kk++) {
            unsigned int af[4][4], bf[4][4];
            #pragma unroll
            for (int mt = 0; mt < 4; mt++)
                ldsm4(af[mt], aBase + (unsigned int)(mt * 16 * LDT * 4 + kk * 32));
            #pragma unroll
            for (int j2 = 0; j2 < 2; j2++)
                ldsm4(bf[j2], bBase + (unsigned int)(j2 * 16 * LDT * 4 + kk * 32));
            // bf[j2] = {nt=2j2:(b0,b1), nt=2j2+1:(b0,b1)}
            #pragma unroll
            for (int mt = 0; mt < 4; mt++) {
                #pragma unroll
                for (int j2 = 0; j2 < 2; j2++) {
                    mma_tf32(acc[mt][2 * j2],     af[mt], &bf[j2][0]);
                    mma_tf32(acc[mt][2 * j2 + 1], af[mt], &bf[j2][2]);
                }
            }
        }
        __syncthreads();
    }

    #pragma unroll
    for (int mt = 0; mt < 4; mt++) {
        #pragma unroll
        for (int nt = 0; nt < 4; nt++) {
            const int g  = lane >> 2, t4 = lane & 3;
            const int row0 = bm + wm + mt * 16 + g;
            const int col  = bn + wn + nt * 8 + 2 * t4;
            *(float2*)(C + (size_t)row0 * N + col)       = make_float2(acc[mt][nt][0], acc[mt][nt][1]);
            *(float2*)(C + (size_t)(row0 + 8) * N + col) = make_float2(acc[mt][nt][2], acc[mt][nt][3]);
        }
    }
}

// ---------------- RoPE + scatter (emits tf32-canonical q/k/v) ---------------
__global__ void rope_scatter(const float* __restrict__ qkv,
                             const int* __restrict__ positions,
                             float* __restrict__ Qr, float* __restrict__ Kr,
                             float* __restrict__ Vr)
{
    const int NQ = T_ * H_ * 64;
    const int NK = T_ * HKV_ * 64;
    const int NV = T_ * HKV_ * 128;
    int idx = blockIdx.x * 256 + threadIdx.x;
    const double KF = 0.20762050593046014;  // log2(10000)/64

    if (idx < NQ) {
        int i = idx & 63;
        int h = (idx >> 6) & 31;
        int t = idx >> 11;
        int pos = positions[t];
        const float* row = qkv + (size_t)t * NQKV_ + h * 128;
        float x1 = row[i], x2 = row[64 + i];
        double f = (double)pos * exp2(-(double)i * KF);
        double sv, cv; sincos(f, &sv, &cv);
        float c = (float)cv, s = (float)sv;
        int b = t >> 10, si = t & 1023;
        float* out = Qr + (((size_t)(b * H_ + h)) * S_ + si) * 128;
        out[i]      = to_tf32(x1 * c - x2 * s);
        out[64 + i] = to_tf32(x2 * c + x1 * s);
    } else if (idx < NQ + NK) {
        int r = idx - NQ;
        int i = r & 63;
        int h = (r >> 6) & 7;
        int t = r >> 9;
        int pos = positions[t];
        const float* row = qkv + (size_t)t * NQKV_ + H_ * 128 + h * 128;
        float x1 = row[i], x2 = row[64 + i];
        double f = (double)pos * exp2(-(double)i * KF);
        double sv, cv; sincos(f, &sv, &cv);
        float c = (float)cv, s = (float)sv;
        int b = t >> 10, si = t & 1023;
        float* out = Kr + (((size_t)(b * HKV_ + h)) * S_ + si) * 128;
        out[i]      = to_tf32(x1 * c - x2 * s);
        out[64 + i] = to_tf32(x2 * c + x1 * s);
    } else if (idx < NQ + NK + NV) {
        int r = idx - NQ - NK;
        int i = r & 127;
        int h = (r >> 7) & 7;
        int t = r >> 10;
        int b = t >> 10, si = t & 1023;
        Vr[(((size_t)(b * HKV_ + h)) * S_ + si) * 128 + i] =
            to_tf32(qkv[(size_t)t * NQKV_ + (H_ + HKV_) * 128 + h * 128 + i]);
    }
}

// ---------------- flash attention via tf32 mma + ldmatrix -------------------
#define FA_LDQ 132
#define FA_LDK 132
#define FA_LDV 136
#define FA_LDP 68
#define FA_Q_FLOATS (128 * FA_LDQ)
#define FA_K_FLOATS (64 * FA_LDK)
#define FA_V_FLOATS (64 * FA_LDV)
#define FA_P_FLOATS (128 * FA_LDP)
#define FA_SMEM_BYTES ((FA_Q_FLOATS + FA_K_FLOATS + FA_V_FLOATS + FA_P_FLOATS) * 4)

__global__ __launch_bounds__(256) void flash_attn_mma(
    const float* __restrict__ Q, const float* __restrict__ Kg,
    const float* __restrict__ Vg, float* __restrict__ Out)
{
    extern __shared__ float sm[];
    float* Qs = sm;
    float* Ks = Qs + FA_Q_FLOATS;
    float* Vs = Ks + FA_K_FLOATS;
    float* Ps = Vs + FA_V_FLOATS;

    const int qb = blockIdx.x;
    const int bh = blockIdx.y;
    const int b  = bh >> 5;
    const int h  = bh & 31;
    const int hkv = h >> 2;

    const float* Qbase = Q  + ((size_t)bh * S_ + qb * 128) * D_;
    const float* Kbase = Kg + ((size_t)(b * HKV_ + hkv) * S_) * D_;
    const float* Vbase = Vg + ((size_t)(b * HKV_ + hkv) * S_) * D_;

    const int tid  = threadIdx.x;
    const int w    = tid >> 5, lane = tid & 31;
    const int g    = lane >> 2, t4 = lane & 3;
    const int wrow = w * 16;
    const float C = 0.12751743199276533f;   // (1/sqrt(128)) * log2(e)

    const unsigned int sQ = (unsigned int)__cvta_generic_to_shared(Qs);
    const unsigned int sK = (unsigned int)__cvta_generic_to_shared(Ks);
    const unsigned int sV = (unsigned int)__cvta_generic_to_shared(Vs);
    const unsigned int sP = (unsigned int)__cvta_generic_to_shared(Ps);

    const int l7  = lane & 7;
    const int lg1 = (lane >> 3) & 1;
    const int lg2 = lane >> 4;
    const unsigned int qLane = (unsigned int)(((wrow + l7 + 8 * lg1) * FA_LDQ + 4 * lg2) * 4);
    const unsigned int kLane = (unsigned int)(((l7 + 8 * lg2) * FA_LDK + 4 * lg1) * 4);
    const unsigned int pLane = (unsigned int)(((wrow + l7 + 8 * lg1) * FA_LDP + 4 * lg2) * 4);

    // load Q tile (128x128)
    for (int i = tid; i < 128 * 32; i += 256) {
        int r = i >> 5, c = (i & 31) << 2;
        *(float4*)&Qs[r * FA_LDQ + c] = *(const float4*)(Qbase + r * 128 + c);
    }

    float O[16][4];
    #pragma unroll
    for (int n = 0; n < 16; n++)
        #pragma unroll
        for (int r = 0; r < 4; r++) O[n][r] = 0.f;
    float m0 = -1e30f, m1 = -1e30f, l0 = 0.f, l1 = 0.f;

    const int jmax = 2 * qb + 1;
    for (int j = 0; j <= jmax; j++) {
        __syncthreads();   // prior PV reads of Ks/Vs done
        for (int i = tid; i < 64 * 32; i += 256) {
            int r = i >> 5, c = (i & 31) << 2;
            cp16(sK + (unsigned int)((r * FA_LDK + c) * 4), Kbase + (j * 64 + r) * 128 + c);
            cp16(sV + (unsigned int)((r * FA_LDV + c) * 4), Vbase + (j * 64 + r) * 128 + c);
        }
        asm volatile("cp.async.commit_group;");
        asm volatile("cp.async.wait_group 0;");
        __syncthreads();

        if (j * 64 > qb * 128 + wrow + 15) continue;

        // ---- S = Q Kt ----
        float sfr[8][4];
        #pragma unroll
        for (int n = 0; n < 8; n++)
            #pragma unroll
            for (int r = 0; r < 4; r++) sfr[n][r] = 0.f;

        #pragma unroll
        for (int kc = 0; kc < 16; kc++) {
            unsigned int a[4];
            ldsm4(a, sQ + qLane + (unsigned int)(kc * 32));
            #pragma unroll
            for (int j2 = 0; j2 < 4; j2++) {
                unsigned int bfr[4];
                ldsm4(bfr, sK + kLane + (unsigned int)(j2 * 16 * FA_LDK * 4 + kc * 32));
                mma_tf32(sfr[2 * j2],     a, &bfr[0]);
                mma_tf32(sfr[2 * j2 + 1], a, &bfr[2]);
            }
        }

        // ---- causal mask ----
        const int qpos0 = qb * 128 + wrow + g;
        const int qpos1 = qpos0 + 8;
        if (j * 64 + 63 > qb * 128 + wrow) {
            #pragma unroll
            for (int nt = 0; nt < 8; nt++) {
                const int kc0 = j * 64 + nt * 8 + 2 * t4;
                if (kc0     > qpos0) sfr[nt][0] = -1e30f;
                if (kc0 + 1 > qpos0) sfr[nt][1] = -1e30f;
                if (kc0     > qpos1) sfr[nt][2] = -1e30f;
                if (kc0 + 1 > qpos1) sfr[nt][3] = -1e30f;
            }
        }

        // ---- online softmax ----
        float rm0 = -1e30f, rm1 = -1e30f;
        #pragma unroll
        for (int nt = 0; nt < 8; nt++) {
            rm0 = fmaxf(rm0, fmaxf(sfr[nt][0], sfr[nt][1]));
            rm1 = fmaxf(rm1, fmaxf(sfr[nt][2], sfr[nt][3]));
        }
        rm0 = fmaxf(rm0, __shfl_xor_sync(0xffffffffu, rm0, 1));
        rm0 = fmaxf(rm0, __shfl_xor_sync(0xffffffffu, rm0, 2));
        rm1 = fmaxf(rm1, __shfl_xor_sync(0xffffffffu, rm1, 1));
        rm1 = fmaxf(rm1, __shfl_xor_sync(0xffffffffu, rm1, 2));

        const float mn0 = fmaxf(m0, rm0);
        const float mn1 = fmaxf(m1, rm1);
        const float corr0 = exp2f((m0 - mn0) * C);
        const float corr1 = exp2f((m1 - mn1) * C);
        #pragma unroll
        for (int nt = 0; nt < 16; nt++) {
            O[nt][0] *= corr0; O[nt][1] *= corr0;
            O[nt][2] *= corr1; O[nt][3] *= corr1;
        }

        float ls0 = 0.f, ls1 = 0.f;
        #pragma unroll
        for (int nt = 0; nt < 8; nt++) {
            float p00 = to_tf32(exp2f((sfr[nt][0] - mn0) * C));
            float p01 = to_tf32(exp2f((sfr[nt][1] - mn0) * C));
            float p10 = to_tf32(exp2f((sfr[nt][2] - mn1) * C));
            float p11 = to_tf32(exp2f((sfr[nt][3] - mn1) * C));
            ls0 += p00 + p01;
            ls1 += p10 + p11;
            const int col = nt * 8 + 2 * t4;
            *(float2*)&Ps[(wrow + g)     * FA_LDP + col] = make_float2(p00, p01);
            *(float2*)&Ps[(wrow + g + 8) * FA_LDP + col] = make_float2(p10, p11);
        }
        ls0 += __shfl_xor_sync(0xffffffffu, ls0, 1);
        ls0 += __shfl_xor_sync(0xffffffffu, ls0, 2);
        ls1 += __shfl_xor_sync(0xffffffffu, ls1, 1);
        ls1 += __shfl_xor_sync(0xffffffffu, ls1, 2);
        l0 = l0 * corr0 + ls0;
        l1 = l1 * corr1 + ls1;
        m0 = mn0; m1 = mn1;

        __syncwarp();   // P rows are warp-private

        // ---- O += P V ----
        #pragma unroll
        for (int kc = 0; kc < 8; kc++) {
            const int k8 = kc * 8;
            unsigned int a[4];
            ldsm4(a, sP + pLane + (unsigned int)(kc * 32));
            #pragma unroll
            for (int nt = 0; nt < 16; nt++) {
                unsigned int bfr[2];
                bfr[0] = __float_as_uint(Vs[(k8 + t4)     * FA_LDV + nt * 8 + g]);
                bfr[1] = __float_as_uint(Vs[(k8 + t4 + 4) * FA_LDV + nt * 8 + g]);
                mma_tf32(O[nt], a, bfr);
            }
        }
    }

    // ---- epilogue ----
    const float il0 = 1.f / l0;
    const float il1 = 1.f / l1;
    const int trow = b * S_ + qb * 128 + wrow + g;
    float* o0 = Out + (size_t)trow * HID_ + h * 128;
    float* o1 = o0 + (size_t)8 * HID_;
    #pragma unroll
    for (int nt = 0; nt < 16; nt++) {
        const int col = nt * 8 + 2 * t4;
        *(float2*)(o0 + col) = make_float2(to_tf32(O[nt][0] * il0), to_tf32(O[nt][1] * il0));
        *(float2*)(o1 + col) = make_float2(to_tf32(O[nt][2] * il1), to_tf32(O[nt][3] * il1));
    }
}

// ---------------- launch -----------------------------------------------------
extern "C" void kernel_launch(void* const* d_in, const int* in_sizes, int n_in,
                              void* d_out, int out_size)
{
    const int*   positions = (const int*)d_in[0];
    const float* hidden    = (const float*)d_in[1];
    const float* w_qkv     = (const float*)d_in[2];
    const float* w_dense   = (const float*)d_in[3];
    float*       out       = (float*)d_out;

    float *qkv, *q, *k, *v, *attn, *hid_r, *wqkv_r, *wd_r;
    cudaGetSymbolAddress((void**)&qkv,    g_qkv);
    cudaGetSymbolAddress((void**)&q,      g_q);
    cudaGetSymbolAddress((void**)&k,      g_k);
    cudaGetSymbolAddress((void**)&v,      g_v);
    cudaGetSymbolAddress((void**)&attn,   g_attn);
    cudaGetSymbolAddress((void**)&hid_r,  g_hid_r);
    cudaGetSymbolAddress((void**)&wqkv_r, g_wqkv_r);
    cudaGetSymbolAddress((void**)&wd_r,   g_wd_r);

    // 0) pre-round GEMM operands to canonical tf32
    {
        int n4;
        n4 = (T_ * HID_) / 4;
        round_tf32_kernel<<<(n4 + 255) / 256, 256>>>(hidden, hid_r, n4);
        n4 = (NQKV_ * HID_) / 4;
        round_tf32_kernel<<<(n4 + 255) / 256, 256>>>(w_qkv, wqkv_r, n4);
        n4 = (HID_ * HID_) / 4;
        round_tf32_kernel<<<(n4 + 255) / 256, 256>>>(w_dense, wd_r, n4);
    }

    // 1) QKV projection
    cudaFuncSetAttribute(tf32_gemm_nt, cudaFuncAttributeMaxDynamicSharedMemorySize,
                         GEMM_SMEM_BYTES);
    tf32_gemm_nt<<<dim3(NQKV_ / BN, T_ / BM), 256, GEMM_SMEM_BYTES>>>(
        hid_r, wqkv_r, qkv, T_, NQKV_, HID_);

    // 2) RoPE + scatter (tf32-canonical outputs)
    const int n_rope = T_ * H_ * 64 + T_ * HKV_ * 64 + T_ * HKV_ * 128;
    rope_scatter<<<(n_rope + 255) / 256, 256>>>(qkv, positions, q, k, v);

    // 3) flash attention
    cudaFuncSetAttribute(flash_attn_mma, cudaFuncAttributeMaxDynamicSharedMemorySize,
                         FA_SMEM_BYTES);
    flash_attn_mma<<<dim3(S_ / 128, B_ * H_), 256, FA_SMEM_BYTES>>>(q, k, v, attn);

    // 4) dense projection
    tf32_gemm_nt<<<dim3(HID_ / BN, T_ / BM), 256, GEMM_SMEM_BYTES>>>(
        attn, wd_r, out, T_, HID_, HID_);
}